// round 1
// baseline (speedup 1.0000x reference)
#include <cuda_runtime.h>
#include <cuda_bf16.h>

#define N_NODES   100000
#define N_EDGES   625000
#define HIDDEN    128
#define N_LAYERS  4
#define NUM_GRAPHS 512

// Scratch (device globals; allocation inside kernel_launch is forbidden)
__device__ float d_h[N_NODES * HIDDEN];
__device__ float d_agg[N_NODES * HIDDEN];
__device__ float d_z[N_NODES * HIDDEN];
__device__ float d_g[NUM_GRAPHS * HIDDEN];

__device__ __forceinline__ float* sel_buf(int s) {
    return s == 0 ? d_h : (s == 1 ? d_agg : d_z);
}

// ---------------------------------------------------------------------------
// h[i, :] = node_emb[x[i], :]    (one float4 per thread)
// ---------------------------------------------------------------------------
__global__ void embed_kernel(const int* __restrict__ x,
                             const float* __restrict__ node_emb) {
    int t = blockIdx.x * blockDim.x + threadIdx.x;
    if (t >= N_NODES * 32) return;
    int node = t >> 5;
    int c4 = (t & 31) << 2;
    int row = __ldg(&x[node]);
    float4 v = *(const float4*)&node_emb[row * HIDDEN + c4];
    *(float4*)&d_h[node * HIDDEN + c4] = v;
}

// agg = h  (so scatter-add produces agg = h + sum_{e:dst=i} h[src])
__global__ void copy_h_to_agg() {
    int t = blockIdx.x * blockDim.x + threadIdx.x;
    if (t >= N_NODES * HIDDEN / 4) return;
    *(float4*)&d_agg[t * 4] = *(const float4*)&d_h[t * 4];
}

// ---------------------------------------------------------------------------
// One warp per edge: agg[dst, :] += h[src, :] via 128-bit vector reductions
// ---------------------------------------------------------------------------
__global__ void scatter_kernel(const int* __restrict__ src,
                               const int* __restrict__ dst) {
    int t = blockIdx.x * blockDim.x + threadIdx.x;
    int edge = t >> 5;
    if (edge >= N_EDGES) return;
    int lane = t & 31;
    int s = __ldg(&src[edge]);
    int d = __ldg(&dst[edge]);
    float4 v = *(const float4*)&d_h[s * HIDDEN + (lane << 2)];
    float* p = &d_agg[d * HIDDEN + (lane << 2)];
    asm volatile("red.global.add.v4.f32 [%0], {%1,%2,%3,%4};"
                 :: "l"(p), "f"(v.x), "f"(v.y), "f"(v.z), "f"(v.w)
                 : "memory");
}

// ---------------------------------------------------------------------------
// C[M,128] = act(A[M,128] @ W[128,128] + bias)    SIMT SGEMM 128x128, BK=8
// ---------------------------------------------------------------------------
template <bool RELU>
__global__ __launch_bounds__(256) void gemm_kernel(
    int asel, int csel,
    const float* __restrict__ W, const float* __restrict__ bias) {
    const float* __restrict__ A = sel_buf(asel);
    float* __restrict__ C = sel_buf(csel);

    __shared__ float As[8][128];
    __shared__ float Bs[8][128];

    int tid = threadIdx.x;
    int bm = blockIdx.x * 128;

    int a_row  = tid >> 1;
    int a_koff = (tid & 1) << 2;
    int b_k = tid >> 5;
    int b_n = (tid & 31) << 2;

    int tr = tid >> 4;   // 0..15 -> rows
    int tc = tid & 15;   // 0..15 -> cols

    int arow_g = bm + a_row;
    if (arow_g >= N_NODES) arow_g = N_NODES - 1;   // clamp load, guard store

    float acc[8][8];
#pragma unroll
    for (int i = 0; i < 8; i++)
#pragma unroll
        for (int j = 0; j < 8; j++) acc[i][j] = 0.f;

    for (int kk = 0; kk < 128; kk += 8) {
        float4 av = *(const float4*)&A[arow_g * 128 + kk + a_koff];
        float4 bv = *(const float4*)&W[(kk + b_k) * 128 + b_n];
        As[a_koff + 0][a_row] = av.x;
        As[a_koff + 1][a_row] = av.y;
        As[a_koff + 2][a_row] = av.z;
        As[a_koff + 3][a_row] = av.w;
        *(float4*)&Bs[b_k][b_n] = bv;
        __syncthreads();
#pragma unroll
        for (int k = 0; k < 8; k++) {
            float4 a0 = *(const float4*)&As[k][tr * 8];
            float4 a1 = *(const float4*)&As[k][tr * 8 + 4];
            float4 b0 = *(const float4*)&Bs[k][tc * 8];
            float4 b1 = *(const float4*)&Bs[k][tc * 8 + 4];
            float a[8] = {a0.x, a0.y, a0.z, a0.w, a1.x, a1.y, a1.z, a1.w};
            float b[8] = {b0.x, b0.y, b0.z, b0.w, b1.x, b1.y, b1.z, b1.w};
#pragma unroll
            for (int i = 0; i < 8; i++)
#pragma unroll
                for (int j = 0; j < 8; j++) acc[i][j] = fmaf(a[i], b[j], acc[i][j]);
        }
        __syncthreads();
    }

    float bj[8];
#pragma unroll
    for (int j = 0; j < 8; j++) bj[j] = __ldg(&bias[tc * 8 + j]);

#pragma unroll
    for (int i = 0; i < 8; i++) {
        int row = bm + tr * 8 + i;
        if (row < N_NODES) {
#pragma unroll
            for (int j4 = 0; j4 < 2; j4++) {
                float4 o;
                o.x = acc[i][j4 * 4 + 0] + bj[j4 * 4 + 0];
                o.y = acc[i][j4 * 4 + 1] + bj[j4 * 4 + 1];
                o.z = acc[i][j4 * 4 + 2] + bj[j4 * 4 + 2];
                o.w = acc[i][j4 * 4 + 3] + bj[j4 * 4 + 3];
                if (RELU) {
                    o.x = fmaxf(o.x, 0.f); o.y = fmaxf(o.y, 0.f);
                    o.z = fmaxf(o.z, 0.f); o.w = fmaxf(o.w, 0.f);
                }
                *(float4*)&C[row * 128 + tc * 8 + j4 * 4] = o;
            }
        }
    }
}

// ---------------------------------------------------------------------------
// Graph pooling: g[batch[i], :] += h[i, :]
// ---------------------------------------------------------------------------
__global__ void zero_g_kernel() {
    int t = blockIdx.x * blockDim.x + threadIdx.x;
    if (t < NUM_GRAPHS * HIDDEN) d_g[t] = 0.f;
}

__global__ void pool_kernel(const int* __restrict__ batch) {
    int t = blockIdx.x * blockDim.x + threadIdx.x;
    int node = t >> 5;
    if (node >= N_NODES) return;
    int lane = t & 31;
    int gidx = __ldg(&batch[node]);
    float4 v = *(const float4*)&d_h[node * HIDDEN + (lane << 2)];
    float* p = &d_g[gidx * HIDDEN + (lane << 2)];
    asm volatile("red.global.add.v4.f32 [%0], {%1,%2,%3,%4};"
                 :: "l"(p), "f"(v.x), "f"(v.y), "f"(v.z), "f"(v.w)
                 : "memory");
}

// ---------------------------------------------------------------------------
// MLP head: 128 -> 64 (relu) -> 32 (relu) -> 1, one block per graph
// ---------------------------------------------------------------------------
__global__ __launch_bounds__(64) void mlp_kernel(
    const float* __restrict__ W1, const float* __restrict__ b1,
    const float* __restrict__ W2, const float* __restrict__ b2,
    const float* __restrict__ W3, const float* __restrict__ b3,
    float* __restrict__ out) {
    __shared__ float sg[128];
    __shared__ float s1[64];
    int g = blockIdx.x;
    int tid = threadIdx.x;

    sg[tid]      = d_g[g * 128 + tid];
    sg[tid + 64] = d_g[g * 128 + 64 + tid];
    __syncthreads();

    float acc = __ldg(&b1[tid]);
#pragma unroll 8
    for (int k = 0; k < 128; k++) acc = fmaf(sg[k], W1[k * 64 + tid], acc);
    s1[tid] = fmaxf(acc, 0.f);
    __syncthreads();

    if (tid < 32) {
        float a2 = __ldg(&b2[tid]);
#pragma unroll 8
        for (int k = 0; k < 64; k++) a2 = fmaf(s1[k], W2[k * 32 + tid], a2);
        a2 = fmaxf(a2, 0.f);
        float t3 = a2 * __ldg(&W3[tid]);
#pragma unroll
        for (int o = 16; o; o >>= 1) t3 += __shfl_down_sync(0xffffffffu, t3, o);
        if (tid == 0) out[g] = t3 + __ldg(&b3[0]);
    }
}

// ---------------------------------------------------------------------------
extern "C" void kernel_launch(void* const* d_in, const int* in_sizes, int n_in,
                              void* d_out, int out_size) {
    const int*   x        = (const int*)d_in[0];
    const int*   edge_idx = (const int*)d_in[1];
    const int*   src      = edge_idx;
    const int*   dst      = edge_idx + N_EDGES;
    const int*   batch    = (const int*)d_in[3];
    const float* node_emb = (const float*)d_in[4];
    // d_in[2] (edge_attr) and d_in[5] (edge_emb) are dead in the reference.
    const float* conv_W1  = (const float*)d_in[6];
    const float* conv_b1  = (const float*)d_in[7];
    const float* conv_W2  = (const float*)d_in[8];
    const float* conv_b2  = (const float*)d_in[9];
    const float* mlp_W1   = (const float*)d_in[10];
    const float* mlp_b1   = (const float*)d_in[11];
    const float* mlp_W2   = (const float*)d_in[12];
    const float* mlp_b2   = (const float*)d_in[13];
    const float* mlp_W3   = (const float*)d_in[14];
    const float* mlp_b3   = (const float*)d_in[15];
    float* out = (float*)d_out;

    const int gemm_grid = (N_NODES + 127) / 128;

    embed_kernel<<<(N_NODES * 32 + 255) / 256, 256>>>(x, node_emb);

    for (int l = 0; l < N_LAYERS; l++) {
        copy_h_to_agg<<<(N_NODES * HIDDEN / 4 + 255) / 256, 256>>>();
        scatter_kernel<<<(N_EDGES * 32 + 255) / 256, 256>>>(src, dst);
        // z = relu((agg) @ W1 + b1)   [agg already includes +h]
        gemm_kernel<true><<<gemm_grid, 256>>>(
            1, 2, conv_W1 + l * HIDDEN * HIDDEN, conv_b1 + l * HIDDEN);
        // h = z @ W2 + b2
        gemm_kernel<false><<<gemm_grid, 256>>>(
            2, 0, conv_W2 + l * HIDDEN * HIDDEN, conv_b2 + l * HIDDEN);
    }

    zero_g_kernel<<<(NUM_GRAPHS * HIDDEN + 255) / 256, 256>>>();
    pool_kernel<<<(N_NODES * 32 + 255) / 256, 256>>>(batch);
    mlp_kernel<<<NUM_GRAPHS, 64>>>(mlp_W1, mlp_b1, mlp_W2, mlp_b2,
                                   mlp_W3, mlp_b3, out);
}

// round 3
// speedup vs baseline: 1.6754x; 1.6754x over previous
#include <cuda_runtime.h>
#include <cuda_bf16.h>
#include <cstdint>

#define N_NODES   100000
#define N_EDGES   625000
#define HIDDEN    128
#define N_LAYERS  4
#define NUM_GRAPHS 512
#define GRID_M    ((N_NODES + 127) / 128)

// Scratch (device globals; allocation inside kernel_launch is forbidden)
__device__ float d_h[N_NODES * HIDDEN];
__device__ float d_agg[N_NODES * HIDDEN];
__device__ float d_z[N_NODES * HIDDEN];
__device__ float d_g[NUM_GRAPHS * HIDDEN];
// Pre-transposed bf16 hi/lo split conv weights: [8 mats][n=128][k=128]
__device__ __nv_bfloat16 d_WBhi[8 * HIDDEN * HIDDEN];
__device__ __nv_bfloat16 d_WBlo[8 * HIDDEN * HIDDEN];
// CSR (by dst) machinery
__device__ int d_deg[N_NODES];
__device__ int d_rowptr[N_NODES + 1];
__device__ int d_wpos[N_NODES];
__device__ int d_csr_src[N_EDGES];

__device__ __forceinline__ float* sel_buf(int s) {
    return s == 0 ? d_h : (s == 1 ? d_agg : d_z);
}

__device__ __forceinline__ uint32_t smem_u32(const void* p) {
    uint32_t a;
    asm("{ .reg .u64 t; cvta.to.shared.u64 t, %1; cvt.u32.u64 %0, t; }"
        : "=r"(a) : "l"(p));
    return a;
}
// SW128-style swizzle for 128B rows: XOR row%8 into the 16B-lane bits
__device__ __forceinline__ uint32_t swz(uint32_t b) {
    return b ^ ((b >> 3) & 0x70);
}

// ---------------------------------------------------------------------------
// Weight prep: WB[mat][n][k] = split(W[l][k][n]) into bf16 hi/lo
// ---------------------------------------------------------------------------
__global__ void prep_w_kernel(const float* __restrict__ W1,
                              const float* __restrict__ W2) {
    int t = blockIdx.x * blockDim.x + threadIdx.x;
    if (t >= 8 * HIDDEN * HIDDEN) return;
    int mat = t >> 14;
    int idx = t & 16383;
    int n = idx & 127;
    int k = idx >> 7;
    int l = mat >> 1;
    const float* W = (mat & 1) ? W2 : W1;
    float v = W[l * HIDDEN * HIDDEN + k * HIDDEN + n];
    __nv_bfloat16 hi = __float2bfloat16(v);
    float lo = v - __bfloat162float(hi);
    d_WBhi[mat * 16384 + n * 128 + k] = hi;
    d_WBlo[mat * 16384 + n * 128 + k] = __float2bfloat16(lo);
}

// ---------------------------------------------------------------------------
// mma.sync bf16 (3-term split) GEMM: C[M,128] = act(A[M,128] @ W + bias)
// CTA: 128 rows x 128 cols, 256 threads (8 warps, each 32x64).
// K processed in two 64-chunks through swizzled smem + ldmatrix.
// ---------------------------------------------------------------------------
__device__ __forceinline__ void mma_bf16(float* c, const uint32_t* a,
                                         const uint32_t* b) {
    asm volatile(
        "mma.sync.aligned.m16n8k16.row.col.f32.bf16.bf16.f32 "
        "{%0,%1,%2,%3}, {%4,%5,%6,%7}, {%8,%9}, {%0,%1,%2,%3};"
        : "+f"(c[0]), "+f"(c[1]), "+f"(c[2]), "+f"(c[3])
        : "r"(a[0]), "r"(a[1]), "r"(a[2]), "r"(a[3]), "r"(b[0]), "r"(b[1]));
}
#define LDSM_X4(r, addr) \
    asm volatile("ldmatrix.sync.aligned.m8n8.x4.shared.b16 {%0,%1,%2,%3}, [%4];" \
                 : "=r"((r)[0]), "=r"((r)[1]), "=r"((r)[2]), "=r"((r)[3]) \
                 : "r"(addr))
#define LDSM_X2(r, addr) \
    asm volatile("ldmatrix.sync.aligned.m8n8.x2.shared.b16 {%0,%1}, [%2];" \
                 : "=r"((r)[0]), "=r"((r)[1]) : "r"(addr))

template <bool RELU>
__global__ __launch_bounds__(256, 2) void gemm_mma(
    int asel, int csel, int widx, const float* __restrict__ bias) {
    const float* __restrict__ A = sel_buf(asel);
    float* __restrict__ C = sel_buf(csel);
    const __nv_bfloat16* __restrict__ Bhi = d_WBhi + widx * 16384;
    const __nv_bfloat16* __restrict__ Blo = d_WBlo + widx * 16384;

    extern __shared__ char sm[];            // 64KB: Ahi|Alo|Bhi|Blo, 16KB each
    uint32_t sbase = smem_u32(sm);

    int tid = threadIdx.x;
    int lane = tid & 31;
    int wid = tid >> 5;
    int wm = (wid & 3) * 32;
    int wn = (wid >> 2) * 64;
    int bm = blockIdx.x * 128;

    float acc[2][8][4];
#pragma unroll
    for (int i = 0; i < 2; i++)
#pragma unroll
        for (int j = 0; j < 8; j++)
#pragma unroll
            for (int q = 0; q < 4; q++) acc[i][j][q] = 0.f;

    for (int ch = 0; ch < 2; ch++) {
        int k0 = ch * 64;
        if (ch) __syncthreads();
        // ---- stage chunk: A (fp32 -> bf16 hi/lo split) and W (precomputed) ----
#pragma unroll
        for (int it = 0; it < 4; it++) {
            int idx = it * 256 + tid;       // 1024 tasks: 128 rows x 8 col-groups
            int row = idx >> 3;
            int c8 = (idx & 7) * 8;
            int ar = bm + row;
            if (ar >= N_NODES) ar = N_NODES - 1;
            const float4* ap = (const float4*)&A[ar * 128 + k0 + c8];
            float4 v0 = ap[0], v1 = ap[1];
            float vv[8] = {v0.x, v0.y, v0.z, v0.w, v1.x, v1.y, v1.z, v1.w};
            union { __nv_bfloat16 b[8]; uint4 u; } H, L;
#pragma unroll
            for (int j = 0; j < 8; j++) {
                H.b[j] = __float2bfloat16(vv[j]);
                L.b[j] = __float2bfloat16(vv[j] - __bfloat162float(H.b[j]));
            }
            uint32_t off = swz(row * 128 + c8 * 2);
            *(uint4*)(sm + off)         = H.u;
            *(uint4*)(sm + 16384 + off) = L.u;
            *(uint4*)(sm + 32768 + off) = *(const uint4*)&Bhi[row * 128 + k0 + c8];
            *(uint4*)(sm + 49152 + off) = *(const uint4*)&Blo[row * 128 + k0 + c8];
        }
        __syncthreads();

        // ---- compute: 4 k-steps of m16n8k16, 3 split terms each ----
#pragma unroll
        for (int ks = 0; ks < 4; ks++) {
            uint32_t ahi[2][4], alo[2][4];
#pragma unroll
            for (int mi = 0; mi < 2; mi++) {
                int r = wm + mi * 16 + (lane & 15);
                int kc = ks * 16 + (lane >> 4) * 8;
                uint32_t ad = sbase + swz(r * 128 + kc * 2);
                LDSM_X4(ahi[mi], ad);
                LDSM_X4(alo[mi], ad + 16384);
            }
#pragma unroll
            for (int nj = 0; nj < 8; nj++) {
                int nr = wn + nj * 8 + (lane & 7);
                int kc = ks * 16 + ((lane >> 3) & 1) * 8;
                uint32_t bd = sbase + 32768 + swz(nr * 128 + kc * 2);
                uint32_t bh[2], bl[2];
                LDSM_X2(bh, bd);
                LDSM_X2(bl, bd + 16384);
#pragma unroll
                for (int mi = 0; mi < 2; mi++) {
                    mma_bf16(acc[mi][nj], ahi[mi], bh);
                    mma_bf16(acc[mi][nj], ahi[mi], bl);
                    mma_bf16(acc[mi][nj], alo[mi], bh);
                }
            }
        }
    }

    // ---- epilogue: bias + relu + store (float2 per fragment row) ----
    int g = lane >> 2, tg = lane & 3;
#pragma unroll
    for (int nj = 0; nj < 8; nj++) {
        int col = wn + nj * 8 + tg * 2;
        float2 bb = *(const float2*)&bias[col];
#pragma unroll
        for (int mi = 0; mi < 2; mi++) {
            int r0 = bm + wm + mi * 16 + g;
            float2 o0, o1;
            o0.x = acc[mi][nj][0] + bb.x; o0.y = acc[mi][nj][1] + bb.y;
            o1.x = acc[mi][nj][2] + bb.x; o1.y = acc[mi][nj][3] + bb.y;
            if (RELU) {
                o0.x = fmaxf(o0.x, 0.f); o0.y = fmaxf(o0.y, 0.f);
                o1.x = fmaxf(o1.x, 0.f); o1.y = fmaxf(o1.y, 0.f);
            }
            if (r0 < N_NODES)     *(float2*)&C[r0 * 128 + col] = o0;
            if (r0 + 8 < N_NODES) *(float2*)&C[(r0 + 8) * 128 + col] = o1;
        }
    }
}

// ---------------------------------------------------------------------------
// CSR build (by dst): degree histogram -> 1-block scan -> fill
// ---------------------------------------------------------------------------
__global__ void zero_deg_kernel() {
    int t = blockIdx.x * blockDim.x + threadIdx.x;
    if (t < N_NODES) d_deg[t] = 0;
}
__global__ void hist_kernel(const int* __restrict__ dst) {
    int e = blockIdx.x * blockDim.x + threadIdx.x;
    if (e < N_EDGES) atomicAdd(&d_deg[dst[e]], 1);
}
__global__ __launch_bounds__(1024) void scan_kernel() {
    __shared__ int part[1024];
    const int CH = (N_NODES + 1023) / 1024;   // 98
    int t = threadIdx.x;
    int beg = t * CH, end = min(beg + CH, N_NODES);
    int s = 0;
    for (int i = beg; i < end; i++) s += d_deg[i];
    part[t] = s;
    __syncthreads();
    if (t == 0) {
        int r = 0;
        for (int i = 0; i < 1024; i++) { int v = part[i]; part[i] = r; r += v; }
    }
    __syncthreads();
    int run = part[t];
    for (int i = beg; i < end; i++) {
        int d = d_deg[i];
        d_rowptr[i] = run;
        d_wpos[i] = run;
        run += d;
    }
    if (end == N_NODES && beg < N_NODES) d_rowptr[N_NODES] = run;
}
__global__ void fill_kernel(const int* __restrict__ src,
                            const int* __restrict__ dst) {
    int e = blockIdx.x * blockDim.x + threadIdx.x;
    if (e >= N_EDGES) return;
    int p = atomicAdd(&d_wpos[dst[e]], 1);
    d_csr_src[p] = src[e];
}

// ---------------------------------------------------------------------------
// h[i,:] = node_emb[x[i],:]
// ---------------------------------------------------------------------------
__global__ void embed_kernel(const int* __restrict__ x,
                             const float* __restrict__ node_emb) {
    int t = blockIdx.x * blockDim.x + threadIdx.x;
    if (t >= N_NODES * 32) return;
    int node = t >> 5;
    int c4 = (t & 31) << 2;
    int row = __ldg(&x[node]);
    *(float4*)&d_h[node * HIDDEN + c4] =
        *(const float4*)&node_emb[row * HIDDEN + c4];
}

// ---------------------------------------------------------------------------
// Gather: agg[i,:] = h[i,:] + sum_{e: dst=i} h[src[e],:]   (one warp / node)
// ---------------------------------------------------------------------------
__global__ void gather_kernel() {
    int t = blockIdx.x * blockDim.x + threadIdx.x;
    int node = t >> 5;
    if (node >= N_NODES) return;
    int lane = t & 31;
    int c4 = lane << 2;
    float4 acc = *(const float4*)&d_h[node * HIDDEN + c4];
    int beg = __ldg(&d_rowptr[node]);
    int end = __ldg(&d_rowptr[node + 1]);
    for (int j = beg; j < end; j++) {
        int s = __ldg(&d_csr_src[j]);
        float4 v = *(const float4*)&d_h[s * HIDDEN + c4];
        acc.x += v.x; acc.y += v.y; acc.z += v.z; acc.w += v.w;
    }
    *(float4*)&d_agg[node * HIDDEN + c4] = acc;
}

// ---------------------------------------------------------------------------
// Graph pooling + MLP head
// ---------------------------------------------------------------------------
__global__ void zero_g_kernel() {
    int t = blockIdx.x * blockDim.x + threadIdx.x;
    if (t < NUM_GRAPHS * HIDDEN) d_g[t] = 0.f;
}
__global__ void pool_kernel(const int* __restrict__ batch) {
    int t = blockIdx.x * blockDim.x + threadIdx.x;
    int node = t >> 5;
    if (node >= N_NODES) return;
    int lane = t & 31;
    int gidx = __ldg(&batch[node]);
    float4 v = *(const float4*)&d_h[node * HIDDEN + (lane << 2)];
    float* p = &d_g[gidx * HIDDEN + (lane << 2)];
    asm volatile("red.global.add.v4.f32 [%0], {%1,%2,%3,%4};"
                 :: "l"(p), "f"(v.x), "f"(v.y), "f"(v.z), "f"(v.w)
                 : "memory");
}
__global__ __launch_bounds__(64) void mlp_kernel(
    const float* __restrict__ W1, const float* __restrict__ b1,
    const float* __restrict__ W2, const float* __restrict__ b2,
    const float* __restrict__ W3, const float* __restrict__ b3,
    float* __restrict__ out) {
    __shared__ float sg[128];
    __shared__ float s1[64];
    int g = blockIdx.x;
    int tid = threadIdx.x;

    sg[tid]      = d_g[g * 128 + tid];
    sg[tid + 64] = d_g[g * 128 + 64 + tid];
    __syncthreads();

    float acc = __ldg(&b1[tid]);
#pragma unroll 8
    for (int k = 0; k < 128; k++) acc = fmaf(sg[k], W1[k * 64 + tid], acc);
    s1[tid] = fmaxf(acc, 0.f);
    __syncthreads();

    if (tid < 32) {
        float a2 = __ldg(&b2[tid]);
#pragma unroll 8
        for (int k = 0; k < 64; k++) a2 = fmaf(s1[k], W2[k * 32 + tid], a2);
        a2 = fmaxf(a2, 0.f);
        float t3 = a2 * __ldg(&W3[tid]);
#pragma unroll
        for (int o = 16; o; o >>= 1) t3 += __shfl_down_sync(0xffffffffu, t3, o);
        if (tid == 0) out[g] = t3 + __ldg(&b3[0]);
    }
}

// ---------------------------------------------------------------------------
extern "C" void kernel_launch(void* const* d_in, const int* in_sizes, int n_in,
                              void* d_out, int out_size) {
    const int*   x        = (const int*)d_in[0];
    const int*   edge_idx = (const int*)d_in[1];
    const int*   src      = edge_idx;
    const int*   dst      = edge_idx + N_EDGES;
    const int*   batch    = (const int*)d_in[3];
    const float* node_emb = (const float*)d_in[4];
    // d_in[2] (edge_attr) and d_in[5] (edge_emb) are dead in the reference.
    const float* conv_W1  = (const float*)d_in[6];
    const float* conv_b1  = (const float*)d_in[7];
    const float* conv_W2  = (const float*)d_in[8];
    const float* conv_b2  = (const float*)d_in[9];
    const float* mlp_W1   = (const float*)d_in[10];
    const float* mlp_b1   = (const float*)d_in[11];
    const float* mlp_W2   = (const float*)d_in[12];
    const float* mlp_b2   = (const float*)d_in[13];
    const float* mlp_W3   = (const float*)d_in[14];
    const float* mlp_b3   = (const float*)d_in[15];
    float* out = (float*)d_out;

    const int SMEMB = 65536;
    cudaFuncSetAttribute(gemm_mma<true>,
                         cudaFuncAttributeMaxDynamicSharedMemorySize, SMEMB);
    cudaFuncSetAttribute(gemm_mma<false>,
                         cudaFuncAttributeMaxDynamicSharedMemorySize, SMEMB);

    prep_w_kernel<<<(8 * HIDDEN * HIDDEN + 255) / 256, 256>>>(conv_W1, conv_W2);
    zero_deg_kernel<<<(N_NODES + 255) / 256, 256>>>();
    hist_kernel<<<(N_EDGES + 255) / 256, 256>>>(dst);
    scan_kernel<<<1, 1024>>>();
    fill_kernel<<<(N_EDGES + 255) / 256, 256>>>(src, dst);
    embed_kernel<<<(N_NODES * 32 + 255) / 256, 256>>>(x, node_emb);

    for (int l = 0; l < N_LAYERS; l++) {
        gather_kernel<<<(N_NODES * 32 + 255) / 256, 256>>>();
        // z = relu(agg @ W1 + b1)
        gemm_mma<true><<<GRID_M, 256, SMEMB>>>(1, 2, 2 * l, conv_b1 + l * HIDDEN);
        // h = z @ W2 + b2
        gemm_mma<false><<<GRID_M, 256, SMEMB>>>(2, 0, 2 * l + 1, conv_b2 + l * HIDDEN);
    }

    zero_g_kernel<<<(NUM_GRAPHS * HIDDEN + 255) / 256, 256>>>();
    pool_kernel<<<(N_NODES * 32 + 255) / 256, 256>>>(batch);
    mlp_kernel<<<NUM_GRAPHS, 64>>>(mlp_W1, mlp_b1, mlp_W2, mlp_b2,
                                   mlp_W3, mlp_b3, out);
}

// round 4
// speedup vs baseline: 2.1531x; 1.2851x over previous
#include <cuda_runtime.h>
#include <cuda_bf16.h>
#include <cstdint>

#define N_NODES   100000
#define N_EDGES   625000
#define HIDDEN    128
#define N_LAYERS  4
#define NUM_GRAPHS 512
#define GRID_M    ((N_NODES + 127) / 128)
#define SCAN_BLKS ((N_NODES + 1023) / 1024)   // 98

// Scratch (device globals; allocation inside kernel_launch is forbidden)
__device__ float d_h[N_NODES * HIDDEN];
__device__ float d_agg[N_NODES * HIDDEN];
__device__ float d_z[N_NODES * HIDDEN];
__device__ float d_g[NUM_GRAPHS * HIDDEN];
// Pre-transposed bf16 hi/lo split conv weights: [8 mats][n=128][k=128]
__device__ __nv_bfloat16 d_WBhi[8 * HIDDEN * HIDDEN];
__device__ __nv_bfloat16 d_WBlo[8 * HIDDEN * HIDDEN];
// CSR (by dst) machinery
__device__ int d_deg[N_NODES];
__device__ int d_rowptr[N_NODES + 1];
__device__ int d_wpos[N_NODES];
__device__ int d_csr_src[N_EDGES];
__device__ int d_bsum[SCAN_BLKS];
__device__ int d_boff[SCAN_BLKS];

__device__ __forceinline__ float* sel_buf(int s) {
    return s == 0 ? d_h : (s == 1 ? d_agg : d_z);
}

__device__ __forceinline__ uint32_t smem_u32(const void* p) {
    uint32_t a;
    asm("{ .reg .u64 t; cvta.to.shared.u64 t, %1; cvt.u32.u64 %0, t; }"
        : "=r"(a) : "l"(p));
    return a;
}
// SW128-style swizzle for 128B rows: XOR row%8 into the 16B-lane bits
__device__ __forceinline__ uint32_t swz(uint32_t b) {
    return b ^ ((b >> 3) & 0x70);
}

// ---------------------------------------------------------------------------
// Weight prep: WB[mat][n][k] = split(W[l][k][n]) into bf16 hi/lo
// ---------------------------------------------------------------------------
__global__ void prep_w_kernel(const float* __restrict__ W1,
                              const float* __restrict__ W2) {
    int t = blockIdx.x * blockDim.x + threadIdx.x;
    if (t >= 8 * HIDDEN * HIDDEN) return;
    int mat = t >> 14;
    int idx = t & 16383;
    int n = idx & 127;
    int k = idx >> 7;
    int l = mat >> 1;
    const float* W = (mat & 1) ? W2 : W1;
    float v = W[l * HIDDEN * HIDDEN + k * HIDDEN + n];
    __nv_bfloat16 hi = __float2bfloat16(v);
    float lo = v - __bfloat162float(hi);
    d_WBhi[mat * 16384 + n * 128 + k] = hi;
    d_WBlo[mat * 16384 + n * 128 + k] = __float2bfloat16(lo);
}

// ---------------------------------------------------------------------------
// mma.sync bf16 (3-term split) GEMM: C[M,128] = act(A[M,128] @ W + bias)
// CTA: 128 rows x 128 cols, 256 threads (8 warps, each 32x64).
// ---------------------------------------------------------------------------
__device__ __forceinline__ void mma_bf16(float* c, const uint32_t* a,
                                         const uint32_t* b) {
    asm volatile(
        "mma.sync.aligned.m16n8k16.row.col.f32.bf16.bf16.f32 "
        "{%0,%1,%2,%3}, {%4,%5,%6,%7}, {%8,%9}, {%0,%1,%2,%3};"
        : "+f"(c[0]), "+f"(c[1]), "+f"(c[2]), "+f"(c[3])
        : "r"(a[0]), "r"(a[1]), "r"(a[2]), "r"(a[3]), "r"(b[0]), "r"(b[1]));
}
#define LDSM_X4(r, addr) \
    asm volatile("ldmatrix.sync.aligned.m8n8.x4.shared.b16 {%0,%1,%2,%3}, [%4];" \
                 : "=r"((r)[0]), "=r"((r)[1]), "=r"((r)[2]), "=r"((r)[3]) \
                 : "r"(addr))
#define LDSM_X2(r, addr) \
    asm volatile("ldmatrix.sync.aligned.m8n8.x2.shared.b16 {%0,%1}, [%2];" \
                 : "=r"((r)[0]), "=r"((r)[1]) : "r"(addr))

template <bool RELU>
__global__ __launch_bounds__(256, 2) void gemm_mma(
    int asel, int csel, int widx, const float* __restrict__ bias) {
    const float* __restrict__ A = sel_buf(asel);
    float* __restrict__ C = sel_buf(csel);
    const __nv_bfloat16* __restrict__ Bhi = d_WBhi + widx * 16384;
    const __nv_bfloat16* __restrict__ Blo = d_WBlo + widx * 16384;

    extern __shared__ char sm[];            // 64KB: Ahi|Alo|Bhi|Blo, 16KB each
    uint32_t sbase = smem_u32(sm);

    int tid = threadIdx.x;
    int lane = tid & 31;
    int wid = tid >> 5;
    int wm = (wid & 3) * 32;
    int wn = (wid >> 2) * 64;
    int bm = blockIdx.x * 128;

    float acc[2][8][4];
#pragma unroll
    for (int i = 0; i < 2; i++)
#pragma unroll
        for (int j = 0; j < 8; j++)
#pragma unroll
            for (int q = 0; q < 4; q++) acc[i][j][q] = 0.f;

    for (int ch = 0; ch < 2; ch++) {
        int k0 = ch * 64;
        if (ch) __syncthreads();
        // ---- stage chunk: A (fp32 -> bf16 hi/lo split) and W (precomputed) ----
#pragma unroll
        for (int it = 0; it < 4; it++) {
            int idx = it * 256 + tid;       // 1024 tasks: 128 rows x 8 col-groups
            int row = idx >> 3;
            int c8 = (idx & 7) * 8;
            int ar = bm + row;
            if (ar >= N_NODES) ar = N_NODES - 1;
            const float4* ap = (const float4*)&A[ar * 128 + k0 + c8];
            float4 v0 = ap[0], v1 = ap[1];
            float vv[8] = {v0.x, v0.y, v0.z, v0.w, v1.x, v1.y, v1.z, v1.w};
            union { __nv_bfloat16 b[8]; uint4 u; } H, L;
#pragma unroll
            for (int j = 0; j < 8; j++) {
                H.b[j] = __float2bfloat16(vv[j]);
                L.b[j] = __float2bfloat16(vv[j] - __bfloat162float(H.b[j]));
            }
            uint32_t off = swz(row * 128 + c8 * 2);
            *(uint4*)(sm + off)         = H.u;
            *(uint4*)(sm + 16384 + off) = L.u;
            *(uint4*)(sm + 32768 + off) = *(const uint4*)&Bhi[row * 128 + k0 + c8];
            *(uint4*)(sm + 49152 + off) = *(const uint4*)&Blo[row * 128 + k0 + c8];
        }
        __syncthreads();

        // ---- compute: 4 k-steps of m16n8k16, 3 split terms each ----
#pragma unroll
        for (int ks = 0; ks < 4; ks++) {
            uint32_t ahi[2][4], alo[2][4];
#pragma unroll
            for (int mi = 0; mi < 2; mi++) {
                int r = wm + mi * 16 + (lane & 15);
                int kc = ks * 16 + (lane >> 4) * 8;
                uint32_t ad = sbase + swz(r * 128 + kc * 2);
                LDSM_X4(ahi[mi], ad);
                LDSM_X4(alo[mi], ad + 16384);
            }
#pragma unroll
            for (int nj = 0; nj < 8; nj++) {
                int nr = wn + nj * 8 + (lane & 7);
                int kc = ks * 16 + ((lane >> 3) & 1) * 8;
                uint32_t bd = sbase + 32768 + swz(nr * 128 + kc * 2);
                uint32_t bh[2], bl[2];
                LDSM_X2(bh, bd);
                LDSM_X2(bl, bd + 16384);
#pragma unroll
                for (int mi = 0; mi < 2; mi++) {
                    mma_bf16(acc[mi][nj], ahi[mi], bh);
                    mma_bf16(acc[mi][nj], ahi[mi], bl);
                    mma_bf16(acc[mi][nj], alo[mi], bh);
                }
            }
        }
    }

    // ---- epilogue: bias + relu + store (float2 per fragment row) ----
    int g = lane >> 2, tg = lane & 3;
#pragma unroll
    for (int nj = 0; nj < 8; nj++) {
        int col = wn + nj * 8 + tg * 2;
        float2 bb = *(const float2*)&bias[col];
#pragma unroll
        for (int mi = 0; mi < 2; mi++) {
            int r0 = bm + wm + mi * 16 + g;
            float2 o0, o1;
            o0.x = acc[mi][nj][0] + bb.x; o0.y = acc[mi][nj][1] + bb.y;
            o1.x = acc[mi][nj][2] + bb.x; o1.y = acc[mi][nj][3] + bb.y;
            if (RELU) {
                o0.x = fmaxf(o0.x, 0.f); o0.y = fmaxf(o0.y, 0.f);
                o1.x = fmaxf(o1.x, 0.f); o1.y = fmaxf(o1.y, 0.f);
            }
            if (r0 < N_NODES)     *(float2*)&C[r0 * 128 + col] = o0;
            if (r0 + 8 < N_NODES) *(float2*)&C[(r0 + 8) * 128 + col] = o1;
        }
    }
}

// ---------------------------------------------------------------------------
// CSR build (by dst): histogram -> 3-phase grid scan -> fill
// ---------------------------------------------------------------------------
__global__ void zero_deg_kernel() {
    int t = blockIdx.x * blockDim.x + threadIdx.x;
    if (t < N_NODES) d_deg[t] = 0;
}
__global__ void hist_kernel(const int* __restrict__ dst) {
    int e = blockIdx.x * blockDim.x + threadIdx.x;
    if (e < N_EDGES) atomicAdd(&d_deg[dst[e]], 1);
}

// Phase A: per-block (1024 elems) sums
__global__ __launch_bounds__(1024) void scanA_kernel() {
    __shared__ int ws[32];
    int i = blockIdx.x * 1024 + threadIdx.x;
    int v = (i < N_NODES) ? d_deg[i] : 0;
    int lane = threadIdx.x & 31, w = threadIdx.x >> 5;
#pragma unroll
    for (int o = 16; o; o >>= 1) v += __shfl_down_sync(0xffffffffu, v, o);
    if (lane == 0) ws[w] = v;
    __syncthreads();
    if (w == 0) {
        int s = ws[lane];
#pragma unroll
        for (int o = 16; o; o >>= 1) s += __shfl_down_sync(0xffffffffu, s, o);
        if (lane == 0) d_bsum[blockIdx.x] = s;
    }
}
// Phase B: exclusive scan of block sums (tiny; smem-resident)
__global__ __launch_bounds__(128) void scanB_kernel() {
    __shared__ int s[SCAN_BLKS];
    int t = threadIdx.x;
    if (t < SCAN_BLKS) s[t] = d_bsum[t];
    __syncthreads();
    if (t == 0) {
        int r = 0;
#pragma unroll 4
        for (int i = 0; i < SCAN_BLKS; i++) { int v = s[i]; s[i] = r; r += v; }
    }
    __syncthreads();
    if (t < SCAN_BLKS) d_boff[t] = s[t];
}
// Phase C: per-block exclusive scan + offset -> rowptr, wpos
__global__ __launch_bounds__(1024) void scanC_kernel() {
    __shared__ int ws[32];
    int i = blockIdx.x * 1024 + threadIdx.x;
    int v = (i < N_NODES) ? d_deg[i] : 0;
    int lane = threadIdx.x & 31, w = threadIdx.x >> 5;
    int x = v;
#pragma unroll
    for (int o = 1; o < 32; o <<= 1) {
        int y = __shfl_up_sync(0xffffffffu, x, o);
        if (lane >= o) x += y;
    }
    if (lane == 31) ws[w] = x;
    __syncthreads();
    if (w == 0) {
        int y = ws[lane];
#pragma unroll
        for (int o = 1; o < 32; o <<= 1) {
            int z = __shfl_up_sync(0xffffffffu, y, o);
            if (lane >= o) y += z;
        }
        ws[lane] = y;
    }
    __syncthreads();
    int incl = x + (w ? ws[w - 1] : 0);
    int base = d_boff[blockIdx.x];
    int excl = base + incl - v;
    if (i < N_NODES) {
        d_rowptr[i] = excl;
        d_wpos[i] = excl;
        if (i == N_NODES - 1) d_rowptr[N_NODES] = excl + v;
    }
}

__global__ void fill_kernel(const int* __restrict__ src,
                            const int* __restrict__ dst) {
    int e = blockIdx.x * blockDim.x + threadIdx.x;
    if (e >= N_EDGES) return;
    int p = atomicAdd(&d_wpos[dst[e]], 1);
    d_csr_src[p] = src[e];
}

// ---------------------------------------------------------------------------
// h[i,:] = node_emb[x[i],:]
// ---------------------------------------------------------------------------
__global__ void embed_kernel(const int* __restrict__ x,
                             const float* __restrict__ node_emb) {
    int t = blockIdx.x * blockDim.x + threadIdx.x;
    if (t >= N_NODES * 32) return;
    int node = t >> 5;
    int c4 = (t & 31) << 2;
    int row = __ldg(&x[node]);
    *(float4*)&d_h[node * HIDDEN + c4] =
        *(const float4*)&node_emb[row * HIDDEN + c4];
}

// ---------------------------------------------------------------------------
// Gather: agg[i,:] = h[i,:] + sum_{e: dst=i} h[src[e],:]   (one warp / node)
// ---------------------------------------------------------------------------
__global__ void gather_kernel() {
    int t = blockIdx.x * blockDim.x + threadIdx.x;
    int node = t >> 5;
    if (node >= N_NODES) return;
    int lane = t & 31;
    int c4 = lane << 2;
    float4 acc = *(const float4*)&d_h[node * HIDDEN + c4];
    int beg = __ldg(&d_rowptr[node]);
    int end = __ldg(&d_rowptr[node + 1]);
    for (int j = beg; j < end; j++) {
        int s = __ldg(&d_csr_src[j]);
        float4 v = *(const float4*)&d_h[s * HIDDEN + c4];
        acc.x += v.x; acc.y += v.y; acc.z += v.z; acc.w += v.w;
    }
    *(float4*)&d_agg[node * HIDDEN + c4] = acc;
}

// ---------------------------------------------------------------------------
// Graph pooling + MLP head
// ---------------------------------------------------------------------------
__global__ void zero_g_kernel() {
    int t = blockIdx.x * blockDim.x + threadIdx.x;
    if (t < NUM_GRAPHS * HIDDEN) d_g[t] = 0.f;
}
__global__ void pool_kernel(const int* __restrict__ batch) {
    int t = blockIdx.x * blockDim.x + threadIdx.x;
    int node = t >> 5;
    if (node >= N_NODES) return;
    int lane = t & 31;
    int gidx = __ldg(&batch[node]);
    float4 v = *(const float4*)&d_h[node * HIDDEN + (lane << 2)];
    float* p = &d_g[gidx * HIDDEN + (lane << 2)];
    asm volatile("red.global.add.v4.f32 [%0], {%1,%2,%3,%4};"
                 :: "l"(p), "f"(v.x), "f"(v.y), "f"(v.z), "f"(v.w)
                 : "memory");
}
__global__ __launch_bounds__(64) void mlp_kernel(
    const float* __restrict__ W1, const float* __restrict__ b1,
    const float* __restrict__ W2, const float* __restrict__ b2,
    const float* __restrict__ W3, const float* __restrict__ b3,
    float* __restrict__ out) {
    __shared__ float sg[128];
    __shared__ float s1[64];
    int g = blockIdx.x;
    int tid = threadIdx.x;

    sg[tid]      = d_g[g * 128 + tid];
    sg[tid + 64] = d_g[g * 128 + 64 + tid];
    __syncthreads();

    float acc = __ldg(&b1[tid]);
#pragma unroll 8
    for (int k = 0; k < 128; k++) acc = fmaf(sg[k], W1[k * 64 + tid], acc);
    s1[tid] = fmaxf(acc, 0.f);
    __syncthreads();

    if (tid < 32) {
        float a2 = __ldg(&b2[tid]);
#pragma unroll 8
        for (int k = 0; k < 64; k++) a2 = fmaf(s1[k], W2[k * 32 + tid], a2);
        a2 = fmaxf(a2, 0.f);
        float t3 = a2 * __ldg(&W3[tid]);
#pragma unroll
        for (int o = 16; o; o >>= 1) t3 += __shfl_down_sync(0xffffffffu, t3, o);
        if (tid == 0) out[g] = t3 + __ldg(&b3[0]);
    }
}

// ---------------------------------------------------------------------------
extern "C" void kernel_launch(void* const* d_in, const int* in_sizes, int n_in,
                              void* d_out, int out_size) {
    const int*   x        = (const int*)d_in[0];
    const int*   edge_idx = (const int*)d_in[1];
    const int*   src      = edge_idx;
    const int*   dst      = edge_idx + N_EDGES;
    const int*   batch    = (const int*)d_in[3];
    const float* node_emb = (const float*)d_in[4];
    // d_in[2] (edge_attr) and d_in[5] (edge_emb) are dead in the reference.
    const float* conv_W1  = (const float*)d_in[6];
    const float* conv_b1  = (const float*)d_in[7];
    const float* conv_W2  = (const float*)d_in[8];
    const float* conv_b2  = (const float*)d_in[9];
    const float* mlp_W1   = (const float*)d_in[10];
    const float* mlp_b1   = (const float*)d_in[11];
    const float* mlp_W2   = (const float*)d_in[12];
    const float* mlp_b2   = (const float*)d_in[13];
    const float* mlp_W3   = (const float*)d_in[14];
    const float* mlp_b3   = (const float*)d_in[15];
    float* out = (float*)d_out;

    const int SMEMB = 65536;
    cudaFuncSetAttribute(gemm_mma<true>,
                         cudaFuncAttributeMaxDynamicSharedMemorySize, SMEMB);
    cudaFuncSetAttribute(gemm_mma<false>,
                         cudaFuncAttributeMaxDynamicSharedMemorySize, SMEMB);

    prep_w_kernel<<<(8 * HIDDEN * HIDDEN + 255) / 256, 256>>>(conv_W1, conv_W2);
    zero_deg_kernel<<<(N_NODES + 255) / 256, 256>>>();
    hist_kernel<<<(N_EDGES + 255) / 256, 256>>>(dst);
    scanA_kernel<<<SCAN_BLKS, 1024>>>();
    scanB_kernel<<<1, 128>>>();
    scanC_kernel<<<SCAN_BLKS, 1024>>>();
    fill_kernel<<<(N_EDGES + 255) / 256, 256>>>(src, dst);
    embed_kernel<<<(N_NODES * 32 + 255) / 256, 256>>>(x, node_emb);

    for (int l = 0; l < N_LAYERS; l++) {
        gather_kernel<<<(N_NODES * 32 + 255) / 256, 256>>>();
        // z = relu(agg @ W1 + b1)
        gemm_mma<true><<<GRID_M, 256, SMEMB>>>(1, 2, 2 * l, conv_b1 + l * HIDDEN);
        // h = z @ W2 + b2
        gemm_mma<false><<<GRID_M, 256, SMEMB>>>(2, 0, 2 * l + 1, conv_b2 + l * HIDDEN);
    }

    zero_g_kernel<<<(NUM_GRAPHS * HIDDEN + 255) / 256, 256>>>();
    pool_kernel<<<(N_NODES * 32 + 255) / 256, 256>>>(batch);
    mlp_kernel<<<NUM_GRAPHS, 64>>>(mlp_W1, mlp_b1, mlp_W2, mlp_b2,
                                   mlp_W3, mlp_b3, out);
}

// round 6
// speedup vs baseline: 2.1780x; 1.0116x over previous
#include <cuda_runtime.h>
#include <cuda_bf16.h>
#include <cstdint>

#define N_NODES   100000
#define N_EDGES   625000
#define HIDDEN    128
#define N_LAYERS  4
#define NUM_GRAPHS 512
#define GRID_M    ((N_NODES + 127) / 128)
#define SCAN_BLKS ((N_NODES + 1023) / 1024)   // 98

// Scratch (device globals; allocation inside kernel_launch is forbidden)
__device__ float d_h[N_NODES * HIDDEN];
__device__ float d_z[N_NODES * HIDDEN];
__device__ float d_g[NUM_GRAPHS * HIDDEN];
// Pre-transposed bf16 hi/lo split conv weights: [8 mats][n=128][k=128]
__device__ __nv_bfloat16 d_WBhi[8 * HIDDEN * HIDDEN];
__device__ __nv_bfloat16 d_WBlo[8 * HIDDEN * HIDDEN];
// CSR (by dst) machinery
__device__ int d_deg[N_NODES];
__device__ int d_rowptr[N_NODES + 1];
__device__ int d_wpos[N_NODES];
__device__ int d_csr_src[N_EDGES];
__device__ int d_bsum[SCAN_BLKS];
__device__ int d_boff[SCAN_BLKS];

__device__ __forceinline__ float* sel_buf(int s) { return s == 0 ? d_h : d_z; }

__device__ __forceinline__ uint32_t smem_u32(const void* p) {
    uint32_t a;
    asm("{ .reg .u64 t; cvta.to.shared.u64 t, %1; cvt.u32.u64 %0, t; }"
        : "=r"(a) : "l"(p));
    return a;
}
// SW128-style swizzle for 128B rows: XOR bits[9:7] into bits[6:4].
// MUST be applied to the FULL intra-buffer byte offset (row bits participate).
__device__ __forceinline__ uint32_t swz(uint32_t b) {
    return b ^ ((b >> 3) & 0x70);
}

// ---------------------------------------------------------------------------
// Weight prep: WB[mat][n][k] = split(W[l][k][n]) into bf16 hi/lo
// ---------------------------------------------------------------------------
__global__ void prep_w_kernel(const float* __restrict__ W1,
                              const float* __restrict__ W2) {
    int t = blockIdx.x * blockDim.x + threadIdx.x;
    if (t >= 8 * HIDDEN * HIDDEN) return;
    int mat = t >> 14;
    int idx = t & 16383;
    int n = idx & 127;
    int k = idx >> 7;
    int l = mat >> 1;
    const float* W = (mat & 1) ? W2 : W1;
    float v = W[l * HIDDEN * HIDDEN + k * HIDDEN + n];
    __nv_bfloat16 hi = __float2bfloat16(v);
    float lo = v - __bfloat162float(hi);
    d_WBhi[mat * 16384 + n * 128 + k] = hi;
    d_WBlo[mat * 16384 + n * 128 + k] = __float2bfloat16(lo);
}

// ---------------------------------------------------------------------------
// MMA helpers
// ---------------------------------------------------------------------------
__device__ __forceinline__ void mma_bf16(float* c, const uint32_t* a,
                                         const uint32_t* b) {
    asm volatile(
        "mma.sync.aligned.m16n8k16.row.col.f32.bf16.bf16.f32 "
        "{%0,%1,%2,%3}, {%4,%5,%6,%7}, {%8,%9}, {%0,%1,%2,%3};"
        : "+f"(c[0]), "+f"(c[1]), "+f"(c[2]), "+f"(c[3])
        : "r"(a[0]), "r"(a[1]), "r"(a[2]), "r"(a[3]), "r"(b[0]), "r"(b[1]));
}
#define LDSM_X4(r, addr) \
    asm volatile("ldmatrix.sync.aligned.m8n8.x4.shared.b16 {%0,%1,%2,%3}, [%4];" \
                 : "=r"((r)[0]), "=r"((r)[1]), "=r"((r)[2]), "=r"((r)[3]) \
                 : "r"(addr))
#define LDSM_X2(r, addr) \
    asm volatile("ldmatrix.sync.aligned.m8n8.x2.shared.b16 {%0,%1}, [%2];" \
                 : "=r"((r)[0]), "=r"((r)[1]) : "r"(addr))

// smem layout (bytes): A-hi[ch0]=0, A-hi[ch1]=16K, A-lo at +32K, W-hi=64K, W-lo=80K
#define SA_LO 32768
#define SW_HI 65536
#define SW_LO 81920
#define SMEMB 98304

// ---------------------------------------------------------------------------
// Fused layer kernel: gather (+self) -> GEMM1+bias+relu -> GEMM2+bias -> hout
// CTA: 128 nodes, 256 threads (8 warps of 32x64 MMA tiles). All staging in smem.
// ---------------------------------------------------------------------------
template <bool EMB>
__global__ __launch_bounds__(256, 2) void layer_kernel(
    int insel, int outsel, int l,
    const float* __restrict__ b1, const float* __restrict__ b2,
    const int* __restrict__ x, const float* __restrict__ node_emb) {
    const float* __restrict__ hin = sel_buf(insel);
    float* __restrict__ hout = sel_buf(outsel);

    extern __shared__ char sm[];
    uint32_t sbase = smem_u32(sm);

    int tid = threadIdx.x;
    int lane = tid & 31;
    int wid = tid >> 5;
    int wm = (wid & 3) * 32;
    int wn = (wid >> 2) * 64;
    int bm = blockIdx.x * 128;

    // ================= gather: smem A = split(h[node] + sum h[src]) =========
    {
        const float* __restrict__ SRC = EMB ? node_emb : hin;
        int c4 = lane << 2;                 // this lane's 4 columns
        uint32_t chb = (uint32_t)(c4 >> 6) * 16384;
        uint32_t cbyte = (uint32_t)((c4 & 63) << 1);
#pragma unroll 2
        for (int i = 0; i < 16; i++) {
            int row = wid * 16 + i;
            int node = bm + row;
            float4 acc = make_float4(0.f, 0.f, 0.f, 0.f);
            if (node < N_NODES) {
                int self = EMB ? __ldg(&x[node]) : node;
                acc = *(const float4*)&SRC[self * 128 + c4];
                int beg = __ldg(&d_rowptr[node]);
                int end = __ldg(&d_rowptr[node + 1]);
                int j = beg;
                for (; j + 4 <= end; j += 4) {
                    int s0 = __ldg(&d_csr_src[j + 0]);
                    int s1 = __ldg(&d_csr_src[j + 1]);
                    int s2 = __ldg(&d_csr_src[j + 2]);
                    int s3 = __ldg(&d_csr_src[j + 3]);
                    if (EMB) {
                        s0 = __ldg(&x[s0]); s1 = __ldg(&x[s1]);
                        s2 = __ldg(&x[s2]); s3 = __ldg(&x[s3]);
                    }
                    float4 v0 = *(const float4*)&SRC[s0 * 128 + c4];
                    float4 v1 = *(const float4*)&SRC[s1 * 128 + c4];
                    float4 v2 = *(const float4*)&SRC[s2 * 128 + c4];
                    float4 v3 = *(const float4*)&SRC[s3 * 128 + c4];
                    acc.x += (v0.x + v1.x) + (v2.x + v3.x);
                    acc.y += (v0.y + v1.y) + (v2.y + v3.y);
                    acc.z += (v0.z + v1.z) + (v2.z + v3.z);
                    acc.w += (v0.w + v1.w) + (v2.w + v3.w);
                }
                for (; j < end; j++) {
                    int s = __ldg(&d_csr_src[j]);
                    if (EMB) s = __ldg(&x[s]);
                    float4 v = *(const float4*)&SRC[s * 128 + c4];
                    acc.x += v.x; acc.y += v.y; acc.z += v.z; acc.w += v.w;
                }
            }
            // split fp32 -> bf16 hi/lo, store 8B each
            float vv[4] = {acc.x, acc.y, acc.z, acc.w};
            union { __nv_bfloat16 b[4]; uint2 u; } H, L;
#pragma unroll
            for (int q = 0; q < 4; q++) {
                H.b[q] = __float2bfloat16(vv[q]);
                L.b[q] = __float2bfloat16(vv[q] - __bfloat162float(H.b[q]));
            }
            // full-offset swizzle: row bits feed the XOR source
            uint32_t off = chb + swz((uint32_t)(row * 128) + cbyte);
            *(uint2*)(sm + off) = H.u;
            *(uint2*)(sm + SA_LO + off) = L.u;
        }
    }
    __syncthreads();

    // ================= two GEMMs through the tensor pipe =====================
    float acc[2][8][4];
#pragma unroll
    for (int i = 0; i < 2; i++)
#pragma unroll
        for (int j = 0; j < 8; j++)
#pragma unroll
            for (int q = 0; q < 4; q++) acc[i][j][q] = 0.f;

    int g = lane >> 2, tg = lane & 3;

#pragma unroll 1
    for (int gg = 0; gg < 2; gg++) {
        const __nv_bfloat16* __restrict__ Whi = d_WBhi + (2 * l + gg) * 16384;
        const __nv_bfloat16* __restrict__ Wlo = d_WBlo + (2 * l + gg) * 16384;
#pragma unroll 1
        for (int ch = 0; ch < 2; ch++) {
            if (gg || ch) __syncthreads();   // protect sW overwrite
            // stage W chunk (hi/lo, 16KB each)
#pragma unroll
            for (int it = 0; it < 4; it++) {
                int idx = it * 256 + tid;    // 1024 tasks: 128 rows x 8 col-grps
                int row = idx >> 3;
                int c8 = (idx & 7) * 8;
                uint32_t off = swz(row * 128 + c8 * 2);
                *(uint4*)(sm + SW_HI + off) =
                    *(const uint4*)&Whi[row * 128 + ch * 64 + c8];
                *(uint4*)(sm + SW_LO + off) =
                    *(const uint4*)&Wlo[row * 128 + ch * 64 + c8];
            }
            __syncthreads();
            // compute 4 local k-steps
#pragma unroll
            for (int ks = 0; ks < 4; ks++) {
                uint32_t ahi[2][4], alo[2][4];
#pragma unroll
                for (int mi = 0; mi < 2; mi++) {
                    int r = wm + mi * 16 + (lane & 15);
                    int kc = ks * 16 + (lane >> 4) * 8;
                    uint32_t ad = sbase + ch * 16384 + swz(r * 128 + kc * 2);
                    LDSM_X4(ahi[mi], ad);
                    LDSM_X4(alo[mi], ad + SA_LO);
                }
#pragma unroll
                for (int nj = 0; nj < 8; nj++) {
                    int nr = wn + nj * 8 + (lane & 7);
                    int kc = ks * 16 + ((lane >> 3) & 1) * 8;
                    uint32_t bd = sbase + SW_HI + swz(nr * 128 + kc * 2);
                    uint32_t bh[2], bl[2];
                    LDSM_X2(bh, bd);
                    LDSM_X2(bl, bd + 16384);
#pragma unroll
                    for (int mi = 0; mi < 2; mi++) {
                        mma_bf16(acc[mi][nj], ahi[mi], bh);
                        mma_bf16(acc[mi][nj], ahi[mi], bl);
                        mma_bf16(acc[mi][nj], alo[mi], bh);
                    }
                }
            }
        }

        if (gg == 0) {
            // ---- z = relu(acc+b1) -> re-split into smem A buffers ----
            __syncthreads();   // all warps done reading sA
#pragma unroll
            for (int nj = 0; nj < 8; nj++) {
                int col = wn + nj * 8 + tg * 2;
                float2 bb = *(const float2*)&b1[col];
                uint32_t chb = (uint32_t)(col >> 6) * 16384;
                uint32_t cbyte = (uint32_t)((col & 63) * 2);
#pragma unroll
                for (int mi = 0; mi < 2; mi++) {
                    int r0 = wm + mi * 16 + g;
#pragma unroll
                    for (int h = 0; h < 2; h++) {
                        float z0 = fmaxf(acc[mi][nj][h * 2 + 0] + bb.x, 0.f);
                        float z1 = fmaxf(acc[mi][nj][h * 2 + 1] + bb.y, 0.f);
                        union { __nv_bfloat16 b[2]; uint32_t u; } H, L;
                        H.b[0] = __float2bfloat16(z0);
                        L.b[0] = __float2bfloat16(z0 - __bfloat162float(H.b[0]));
                        H.b[1] = __float2bfloat16(z1);
                        L.b[1] = __float2bfloat16(z1 - __bfloat162float(H.b[1]));
                        // full-offset swizzle here too
                        uint32_t off = chb +
                            swz((uint32_t)((r0 + h * 8) * 128) + cbyte);
                        *(uint32_t*)(sm + off) = H.u;
                        *(uint32_t*)(sm + SA_LO + off) = L.u;
                        acc[mi][nj][h * 2 + 0] = 0.f;
                        acc[mi][nj][h * 2 + 1] = 0.f;
                    }
                }
            }
        } else {
            // ---- epilogue: h_out = acc + b2 ----
#pragma unroll
            for (int nj = 0; nj < 8; nj++) {
                int col = wn + nj * 8 + tg * 2;
                float2 bb = *(const float2*)&b2[col];
#pragma unroll
                for (int mi = 0; mi < 2; mi++) {
                    int r0 = bm + wm + mi * 16 + g;
                    float2 o0, o1;
                    o0.x = acc[mi][nj][0] + bb.x; o0.y = acc[mi][nj][1] + bb.y;
                    o1.x = acc[mi][nj][2] + bb.x; o1.y = acc[mi][nj][3] + bb.y;
                    if (r0 < N_NODES)     *(float2*)&hout[r0 * 128 + col] = o0;
                    if (r0 + 8 < N_NODES) *(float2*)&hout[(r0 + 8) * 128 + col] = o1;
                }
            }
        }
    }
}

// ---------------------------------------------------------------------------
// CSR build (by dst): histogram -> 3-phase grid scan -> fill
// ---------------------------------------------------------------------------
__global__ void zero_deg_kernel() {
    int t = blockIdx.x * blockDim.x + threadIdx.x;
    if (t < N_NODES) d_deg[t] = 0;
}
__global__ void hist_kernel(const int* __restrict__ dst) {
    int e = blockIdx.x * blockDim.x + threadIdx.x;
    if (e < N_EDGES) atomicAdd(&d_deg[dst[e]], 1);
}
__global__ __launch_bounds__(1024) void scanA_kernel() {
    __shared__ int ws[32];
    int i = blockIdx.x * 1024 + threadIdx.x;
    int v = (i < N_NODES) ? d_deg[i] : 0;
    int lane = threadIdx.x & 31, w = threadIdx.x >> 5;
#pragma unroll
    for (int o = 16; o; o >>= 1) v += __shfl_down_sync(0xffffffffu, v, o);
    if (lane == 0) ws[w] = v;
    __syncthreads();
    if (w == 0) {
        int s = ws[lane];
#pragma unroll
        for (int o = 16; o; o >>= 1) s += __shfl_down_sync(0xffffffffu, s, o);
        if (lane == 0) d_bsum[blockIdx.x] = s;
    }
}
__global__ __launch_bounds__(128) void scanB_kernel() {
    __shared__ int s[SCAN_BLKS];
    int t = threadIdx.x;
    if (t < SCAN_BLKS) s[t] = d_bsum[t];
    __syncthreads();
    if (t == 0) {
        int r = 0;
#pragma unroll 4
        for (int i = 0; i < SCAN_BLKS; i++) { int v = s[i]; s[i] = r; r += v; }
    }
    __syncthreads();
    if (t < SCAN_BLKS) d_boff[t] = s[t];
}
__global__ __launch_bounds__(1024) void scanC_kernel() {
    __shared__ int ws[32];
    int i = blockIdx.x * 1024 + threadIdx.x;
    int v = (i < N_NODES) ? d_deg[i] : 0;
    int lane = threadIdx.x & 31, w = threadIdx.x >> 5;
    int x = v;
#pragma unroll
    for (int o = 1; o < 32; o <<= 1) {
        int y = __shfl_up_sync(0xffffffffu, x, o);
        if (lane >= o) x += y;
    }
    if (lane == 31) ws[w] = x;
    __syncthreads();
    if (w == 0) {
        int y = ws[lane];
#pragma unroll
        for (int o = 1; o < 32; o <<= 1) {
            int z = __shfl_up_sync(0xffffffffu, y, o);
            if (lane >= o) y += z;
        }
        ws[lane] = y;
    }
    __syncthreads();
    int incl = x + (w ? ws[w - 1] : 0);
    int base = d_boff[blockIdx.x];
    int excl = base + incl - v;
    if (i < N_NODES) {
        d_rowptr[i] = excl;
        d_wpos[i] = excl;
        if (i == N_NODES - 1) d_rowptr[N_NODES] = excl + v;
    }
}
__global__ void fill_kernel(const int* __restrict__ src,
                            const int* __restrict__ dst) {
    int e = blockIdx.x * blockDim.x + threadIdx.x;
    if (e >= N_EDGES) return;
    int p = atomicAdd(&d_wpos[dst[e]], 1);
    d_csr_src[p] = src[e];
}

// ---------------------------------------------------------------------------
// Graph pooling + MLP head
// ---------------------------------------------------------------------------
__global__ void zero_g_kernel() {
    int t = blockIdx.x * blockDim.x + threadIdx.x;
    if (t < NUM_GRAPHS * HIDDEN) d_g[t] = 0.f;
}
__global__ void pool_kernel(const int* __restrict__ batch) {
    int t = blockIdx.x * blockDim.x + threadIdx.x;
    int node = t >> 5;
    if (node >= N_NODES) return;
    int lane = t & 31;
    int gidx = __ldg(&batch[node]);
    float4 v = *(const float4*)&d_h[node * HIDDEN + (lane << 2)];
    float* p = &d_g[gidx * HIDDEN + (lane << 2)];
    asm volatile("red.global.add.v4.f32 [%0], {%1,%2,%3,%4};"
                 :: "l"(p), "f"(v.x), "f"(v.y), "f"(v.z), "f"(v.w)
                 : "memory");
}
__global__ __launch_bounds__(64) void mlp_kernel(
    const float* __restrict__ W1, const float* __restrict__ b1,
    const float* __restrict__ W2, const float* __restrict__ b2,
    const float* __restrict__ W3, const float* __restrict__ b3,
    float* __restrict__ out) {
    __shared__ float sg[128];
    __shared__ float s1[64];
    int g = blockIdx.x;
    int tid = threadIdx.x;

    sg[tid]      = d_g[g * 128 + tid];
    sg[tid + 64] = d_g[g * 128 + 64 + tid];
    __syncthreads();

    float acc = __ldg(&b1[tid]);
#pragma unroll 8
    for (int k = 0; k < 128; k++) acc = fmaf(sg[k], W1[k * 64 + tid], acc);
    s1[tid] = fmaxf(acc, 0.f);
    __syncthreads();

    if (tid < 32) {
        float a2 = __ldg(&b2[tid]);
#pragma unroll 8
        for (int k = 0; k < 64; k++) a2 = fmaf(s1[k], W2[k * 32 + tid], a2);
        a2 = fmaxf(a2, 0.f);
        float t3 = a2 * __ldg(&W3[tid]);
#pragma unroll
        for (int o = 16; o; o >>= 1) t3 += __shfl_down_sync(0xffffffffu, t3, o);
        if (tid == 0) out[g] = t3 + __ldg(&b3[0]);
    }
}

// ---------------------------------------------------------------------------
extern "C" void kernel_launch(void* const* d_in, const int* in_sizes, int n_in,
                              void* d_out, int out_size) {
    const int*   x        = (const int*)d_in[0];
    const int*   edge_idx = (const int*)d_in[1];
    const int*   src      = edge_idx;
    const int*   dst      = edge_idx + N_EDGES;
    const int*   batch    = (const int*)d_in[3];
    const float* node_emb = (const float*)d_in[4];
    // d_in[2] (edge_attr) and d_in[5] (edge_emb) are dead in the reference.
    const float* conv_W1  = (const float*)d_in[6];
    const float* conv_b1  = (const float*)d_in[7];
    const float* conv_W2  = (const float*)d_in[8];
    const float* conv_b2  = (const float*)d_in[9];
    const float* mlp_W1   = (const float*)d_in[10];
    const float* mlp_b1   = (const float*)d_in[11];
    const float* mlp_W2   = (const float*)d_in[12];
    const float* mlp_b2   = (const float*)d_in[13];
    const float* mlp_W3   = (const float*)d_in[14];
    const float* mlp_b3   = (const float*)d_in[15];
    float* out = (float*)d_out;

    cudaFuncSetAttribute(layer_kernel<true>,
                         cudaFuncAttributeMaxDynamicSharedMemorySize, SMEMB);
    cudaFuncSetAttribute(layer_kernel<false>,
                         cudaFuncAttributeMaxDynamicSharedMemorySize, SMEMB);

    prep_w_kernel<<<(8 * HIDDEN * HIDDEN + 255) / 256, 256>>>(conv_W1, conv_W2);
    zero_deg_kernel<<<(N_NODES + 255) / 256, 256>>>();
    hist_kernel<<<(N_EDGES + 255) / 256, 256>>>(dst);
    scanA_kernel<<<SCAN_BLKS, 1024>>>();
    scanB_kernel<<<1, 128>>>();
    scanC_kernel<<<SCAN_BLKS, 1024>>>();
    fill_kernel<<<(N_EDGES + 255) / 256, 256>>>(src, dst);

    // ping-pong: L0 emb->z, L1 z->h, L2 h->z, L3 z->h (pool reads d_h)
    layer_kernel<true><<<GRID_M, 256, SMEMB>>>(
        0, 1, 0, conv_b1 + 0 * HIDDEN, conv_b2 + 0 * HIDDEN, x, node_emb);
    layer_kernel<false><<<GRID_M, 256, SMEMB>>>(
        1, 0, 1, conv_b1 + 1 * HIDDEN, conv_b2 + 1 * HIDDEN, x, node_emb);
    layer_kernel<false><<<GRID_M, 256, SMEMB>>>(
        0, 1, 2, conv_b1 + 2 * HIDDEN, conv_b2 + 2 * HIDDEN, x, node_emb);
    layer_kernel<false><<<GRID_M, 256, SMEMB>>>(
        1, 0, 3, conv_b1 + 3 * HIDDEN, conv_b2 + 3 * HIDDEN, x, node_emb);

    zero_g_kernel<<<(NUM_GRAPHS * HIDDEN + 255) / 256, 256>>>();
    pool_kernel<<<(N_NODES * 32 + 255) / 256, 256>>>(batch);
    mlp_kernel<<<NUM_GRAPHS, 64>>>(mlp_W1, mlp_b1, mlp_W2, mlp_b2,
                                   mlp_W3, mlp_b3, out);
}

// round 7
// speedup vs baseline: 2.5287x; 1.1610x over previous
#include <cuda_runtime.h>
#include <cuda_bf16.h>
#include <cstdint>

#define N_NODES   100000
#define N_EDGES   625000
#define HIDDEN    128
#define N_LAYERS  4
#define NUM_GRAPHS 512
#define GRID_M    ((N_NODES + 127) / 128)
#define SCAN_BLKS ((N_NODES + 1023) / 1024)   // 98

// Scratch (device globals; allocation inside kernel_launch is forbidden)
__device__ float d_zA[N_NODES * HIDDEN];
__device__ float d_zB[N_NODES * HIDDEN];
__device__ float d_g[NUM_GRAPHS * HIDDEN];
__device__ int   d_gcnt[NUM_GRAPHS];
// Composite conv weights, transposed + bf16 hi/lo split: [4 mats][n=128][k=128]
// mat 0 = W1_0^T ; mat l = (W2_{l-1} @ W1_l)^T for l=1..3
__device__ __nv_bfloat16 d_WBhi[4 * HIDDEN * HIDDEN];
__device__ __nv_bfloat16 d_WBlo[4 * HIDDEN * HIDDEN];
__device__ float d_cvec[4 * HIDDEN];   // c_l = b2_{l-1} @ W1_l (c_0 = 0)
// CSR (by dst) machinery
__device__ int d_deg[N_NODES];
__device__ int d_rowptr[N_NODES + 1];
__device__ int d_wpos[N_NODES];
__device__ int d_csr_src[N_EDGES];
__device__ int d_bsum[SCAN_BLKS];
__device__ int d_boff[SCAN_BLKS];

__device__ __forceinline__ float* sel_buf(int s) { return s == 0 ? d_zA : d_zB; }

__device__ __forceinline__ uint32_t smem_u32(const void* p) {
    uint32_t a;
    asm("{ .reg .u64 t; cvta.to.shared.u64 t, %1; cvt.u32.u64 %0, t; }"
        : "=r"(a) : "l"(p));
    return a;
}
// SW128-style swizzle: XOR bits[9:7] into bits[6:4]. Apply to FULL byte offset.
__device__ __forceinline__ uint32_t swz(uint32_t b) {
    return b ^ ((b >> 3) & 0x70);
}

// ---------------------------------------------------------------------------
// Weight prep
// ---------------------------------------------------------------------------
// mat 0: WT[n][k] = W1[0][k][n], split bf16 hi/lo
__global__ void prep_w0_kernel(const float* __restrict__ W1) {
    int t = blockIdx.x * blockDim.x + threadIdx.x;
    if (t >= HIDDEN * HIDDEN) return;
    int n = t & 127, k = t >> 7;
    float v = W1[k * HIDDEN + n];
    __nv_bfloat16 hi = __float2bfloat16(v);
    d_WBhi[n * 128 + k] = hi;
    d_WBlo[n * 128 + k] = __float2bfloat16(v - __bfloat162float(hi));
}
// mats 1..3: WT_l[n][k] = sum_j W2[l-1][k][j] * W1[l][j][n]  (fp32, then split)
__global__ void prep_compose_kernel(const float* __restrict__ W1,
                                    const float* __restrict__ W2) {
    int t = blockIdx.x * blockDim.x + threadIdx.x;
    if (t >= 3 * HIDDEN * HIDDEN) return;
    int l = 1 + (t >> 14);
    int idx = t & 16383;
    int n = idx & 127, k = idx >> 7;
    const float* W2r = W2 + (l - 1) * HIDDEN * HIDDEN + k * HIDDEN;
    const float* W1m = W1 + l * HIDDEN * HIDDEN;
    float s = 0.f;
#pragma unroll 8
    for (int j = 0; j < HIDDEN; j++) s = fmaf(W2r[j], W1m[j * HIDDEN + n], s);
    __nv_bfloat16 hi = __float2bfloat16(s);
    d_WBhi[l * 16384 + n * 128 + k] = hi;
    d_WBlo[l * 16384 + n * 128 + k] = __float2bfloat16(s - __bfloat162float(hi));
}
// c_l[n] = sum_j b2[l-1][j] * W1[l][j][n];  c_0 = 0
__global__ void prep_cvec_kernel(const float* __restrict__ W1,
                                 const float* __restrict__ b2) {
    int t = blockIdx.x * blockDim.x + threadIdx.x;
    if (t >= 4 * HIDDEN) return;
    int l = t >> 7, n = t & 127;
    float s = 0.f;
    if (l > 0) {
        const float* b2r = b2 + (l - 1) * HIDDEN;
        const float* W1m = W1 + l * HIDDEN * HIDDEN;
#pragma unroll 8
        for (int j = 0; j < HIDDEN; j++) s = fmaf(b2r[j], W1m[j * HIDDEN + n], s);
    }
    d_cvec[t] = s;
}

// ---------------------------------------------------------------------------
// MMA helpers
// ---------------------------------------------------------------------------
__device__ __forceinline__ void mma_bf16(float* c, const uint32_t* a,
                                         const uint32_t* b) {
    asm volatile(
        "mma.sync.aligned.m16n8k16.row.col.f32.bf16.bf16.f32 "
        "{%0,%1,%2,%3}, {%4,%5,%6,%7}, {%8,%9}, {%0,%1,%2,%3};"
        : "+f"(c[0]), "+f"(c[1]), "+f"(c[2]), "+f"(c[3])
        : "r"(a[0]), "r"(a[1]), "r"(a[2]), "r"(a[3]), "r"(b[0]), "r"(b[1]));
}
#define LDSM_X4(r, addr) \
    asm volatile("ldmatrix.sync.aligned.m8n8.x4.shared.b16 {%0,%1,%2,%3}, [%4];" \
                 : "=r"((r)[0]), "=r"((r)[1]), "=r"((r)[2]), "=r"((r)[3]) \
                 : "r"(addr))
#define LDSM_X2(r, addr) \
    asm volatile("ldmatrix.sync.aligned.m8n8.x2.shared.b16 {%0,%1}, [%2];" \
                 : "=r"((r)[0]), "=r"((r)[1]) : "r"(addr))

// smem layout (bytes): A-hi[ch0]=0, A-hi[ch1]=16K, A-lo at +32K, W-hi=64K, W-lo=80K
#define SA_LO 32768
#define SW_HI 65536
#define SW_LO 81920
#define SMEMB 98304

// ---------------------------------------------------------------------------
// Fused layer: gather z (+self) -> ONE 3-term GEMM -> relu(.+deg'*c+b1) -> z'
// CTA: 128 nodes, 256 threads (8 warps, 32x64 MMA tiles each).
// ---------------------------------------------------------------------------
template <bool EMB>
__global__ __launch_bounds__(256, 2) void layer_kernel(
    int insel, int outsel, int widx,
    const float* __restrict__ b1,
    const int* __restrict__ x, const float* __restrict__ node_emb) {
    const float* __restrict__ zin = sel_buf(insel);
    float* __restrict__ zout = sel_buf(outsel);
    const float* __restrict__ cvec = d_cvec + widx * HIDDEN;

    extern __shared__ char sm[];
    uint32_t sbase = smem_u32(sm);

    int tid = threadIdx.x;
    int lane = tid & 31;
    int wid = tid >> 5;
    int wm = (wid & 3) * 32;
    int wn = (wid >> 2) * 64;
    int bm = blockIdx.x * 128;

    // ============ gather: smem A = split(z[node] + sum z[src]) ============
    {
        const float* __restrict__ SRC = EMB ? node_emb : zin;
        int c4 = lane << 2;
        uint32_t chb = (uint32_t)(c4 >> 6) * 16384;
        uint32_t cbyte = (uint32_t)((c4 & 63) << 1);
#pragma unroll 2
        for (int i = 0; i < 16; i++) {
            int row = wid * 16 + i;
            int node = bm + row;
            float4 acc = make_float4(0.f, 0.f, 0.f, 0.f);
            if (node < N_NODES) {
                int self = EMB ? __ldg(&x[node]) : node;
                acc = *(const float4*)&SRC[self * 128 + c4];
                int beg = __ldg(&d_rowptr[node]);
                int end = __ldg(&d_rowptr[node + 1]);
                int j = beg;
                for (; j + 4 <= end; j += 4) {
                    int s0 = __ldg(&d_csr_src[j + 0]);
                    int s1 = __ldg(&d_csr_src[j + 1]);
                    int s2 = __ldg(&d_csr_src[j + 2]);
                    int s3 = __ldg(&d_csr_src[j + 3]);
                    if (EMB) {
                        s0 = __ldg(&x[s0]); s1 = __ldg(&x[s1]);
                        s2 = __ldg(&x[s2]); s3 = __ldg(&x[s3]);
                    }
                    float4 v0 = *(const float4*)&SRC[s0 * 128 + c4];
                    float4 v1 = *(const float4*)&SRC[s1 * 128 + c4];
                    float4 v2 = *(const float4*)&SRC[s2 * 128 + c4];
                    float4 v3 = *(const float4*)&SRC[s3 * 128 + c4];
                    acc.x += (v0.x + v1.x) + (v2.x + v3.x);
                    acc.y += (v0.y + v1.y) + (v2.y + v3.y);
                    acc.z += (v0.z + v1.z) + (v2.z + v3.z);
                    acc.w += (v0.w + v1.w) + (v2.w + v3.w);
                }
                for (; j < end; j++) {
                    int s = __ldg(&d_csr_src[j]);
                    if (EMB) s = __ldg(&x[s]);
                    float4 v = *(const float4*)&SRC[s * 128 + c4];
                    acc.x += v.x; acc.y += v.y; acc.z += v.z; acc.w += v.w;
                }
            }
            float vv[4] = {acc.x, acc.y, acc.z, acc.w};
            union { __nv_bfloat16 b[4]; uint2 u; } H, L;
#pragma unroll
            for (int q = 0; q < 4; q++) {
                H.b[q] = __float2bfloat16(vv[q]);
                L.b[q] = __float2bfloat16(vv[q] - __bfloat162float(H.b[q]));
            }
            uint32_t off = chb + swz((uint32_t)(row * 128) + cbyte);
            *(uint2*)(sm + off) = H.u;
            *(uint2*)(sm + SA_LO + off) = L.u;
        }
    }
    __syncthreads();

    // ============ ONE GEMM (3-term split) over 2 K-chunks ============
    float acc[2][8][4];
#pragma unroll
    for (int i = 0; i < 2; i++)
#pragma unroll
        for (int j = 0; j < 8; j++)
#pragma unroll
            for (int q = 0; q < 4; q++) acc[i][j][q] = 0.f;

    const __nv_bfloat16* __restrict__ Whi = d_WBhi + widx * 16384;
    const __nv_bfloat16* __restrict__ Wlo = d_WBlo + widx * 16384;

#pragma unroll 1
    for (int ch = 0; ch < 2; ch++) {
        if (ch) __syncthreads();
#pragma unroll
        for (int it = 0; it < 4; it++) {
            int idx = it * 256 + tid;
            int row = idx >> 3;
            int c8 = (idx & 7) * 8;
            uint32_t off = swz(row * 128 + c8 * 2);
            *(uint4*)(sm + SW_HI + off) =
                *(const uint4*)&Whi[row * 128 + ch * 64 + c8];
            *(uint4*)(sm + SW_LO + off) =
                *(const uint4*)&Wlo[row * 128 + ch * 64 + c8];
        }
        __syncthreads();
#pragma unroll
        for (int ks = 0; ks < 4; ks++) {
            uint32_t ahi[2][4], alo[2][4];
#pragma unroll
            for (int mi = 0; mi < 2; mi++) {
                int r = wm + mi * 16 + (lane & 15);
                int kc = ks * 16 + (lane >> 4) * 8;
                uint32_t ad = sbase + ch * 16384 + swz(r * 128 + kc * 2);
                LDSM_X4(ahi[mi], ad);
                LDSM_X4(alo[mi], ad + SA_LO);
            }
#pragma unroll
            for (int nj = 0; nj < 8; nj++) {
                int nr = wn + nj * 8 + (lane & 7);
                int kc = ks * 16 + ((lane >> 3) & 1) * 8;
                uint32_t bd = sbase + SW_HI + swz(nr * 128 + kc * 2);
                uint32_t bh[2], bl[2];
                LDSM_X2(bh, bd);
                LDSM_X2(bl, bd + 16384);
#pragma unroll
                for (int mi = 0; mi < 2; mi++) {
                    mma_bf16(acc[mi][nj], ahi[mi], bh);
                    mma_bf16(acc[mi][nj], ahi[mi], bl);
                    mma_bf16(acc[mi][nj], alo[mi], bh);
                }
            }
        }
    }

    // ============ epilogue: z' = relu(acc + deg'*c + b1) ============
    int g = lane >> 2, tg = lane & 3;
    float degp[2][2];
#pragma unroll
    for (int mi = 0; mi < 2; mi++)
#pragma unroll
        for (int h = 0; h < 2; h++) {
            int row = bm + wm + mi * 16 + g + h * 8;
            degp[mi][h] = (row < N_NODES)
                ? (float)(__ldg(&d_rowptr[row + 1]) - __ldg(&d_rowptr[row]) + 1)
                : 0.f;
        }
#pragma unroll
    for (int nj = 0; nj < 8; nj++) {
        int col = wn + nj * 8 + tg * 2;
        float2 bb = *(const float2*)&b1[col];
        float2 cv = *(const float2*)&cvec[col];
#pragma unroll
        for (int mi = 0; mi < 2; mi++) {
            int r0 = bm + wm + mi * 16 + g;
            float2 o0, o1;
            o0.x = fmaxf(acc[mi][nj][0] + degp[mi][0] * cv.x + bb.x, 0.f);
            o0.y = fmaxf(acc[mi][nj][1] + degp[mi][0] * cv.y + bb.y, 0.f);
            o1.x = fmaxf(acc[mi][nj][2] + degp[mi][1] * cv.x + bb.x, 0.f);
            o1.y = fmaxf(acc[mi][nj][3] + degp[mi][1] * cv.y + bb.y, 0.f);
            if (r0 < N_NODES)     *(float2*)&zout[r0 * 128 + col] = o0;
            if (r0 + 8 < N_NODES) *(float2*)&zout[(r0 + 8) * 128 + col] = o1;
        }
    }
}

// ---------------------------------------------------------------------------
// CSR build (by dst): histogram -> 3-phase grid scan -> fill
// ---------------------------------------------------------------------------
__global__ void zero_deg_kernel() {
    int t = blockIdx.x * blockDim.x + threadIdx.x;
    if (t < N_NODES) d_deg[t] = 0;
}
__global__ void hist_kernel(const int* __restrict__ dst) {
    int e = blockIdx.x * blockDim.x + threadIdx.x;
    if (e < N_EDGES) atomicAdd(&d_deg[dst[e]], 1);
}
__global__ __launch_bounds__(1024) void scanA_kernel() {
    __shared__ int ws[32];
    int i = blockIdx.x * 1024 + threadIdx.x;
    int v = (i < N_NODES) ? d_deg[i] : 0;
    int lane = threadIdx.x & 31, w = threadIdx.x >> 5;
#pragma unroll
    for (int o = 16; o; o >>= 1) v += __shfl_down_sync(0xffffffffu, v, o);
    if (lane == 0) ws[w] = v;
    __syncthreads();
    if (w == 0) {
        int s = ws[lane];
#pragma unroll
        for (int o = 16; o; o >>= 1) s += __shfl_down_sync(0xffffffffu, s, o);
        if (lane == 0) d_bsum[blockIdx.x] = s;
    }
}
__global__ __launch_bounds__(128) void scanB_kernel() {
    __shared__ int s[SCAN_BLKS];
    int t = threadIdx.x;
    if (t < SCAN_BLKS) s[t] = d_bsum[t];
    __syncthreads();
    if (t == 0) {
        int r = 0;
#pragma unroll 4
        for (int i = 0; i < SCAN_BLKS; i++) { int v = s[i]; s[i] = r; r += v; }
    }
    __syncthreads();
    if (t < SCAN_BLKS) d_boff[t] = s[t];
}
__global__ __launch_bounds__(1024) void scanC_kernel() {
    __shared__ int ws[32];
    int i = blockIdx.x * 1024 + threadIdx.x;
    int v = (i < N_NODES) ? d_deg[i] : 0;
    int lane = threadIdx.x & 31, w = threadIdx.x >> 5;
    int x = v;
#pragma unroll
    for (int o = 1; o < 32; o <<= 1) {
        int y = __shfl_up_sync(0xffffffffu, x, o);
        if (lane >= o) x += y;
    }
    if (lane == 31) ws[w] = x;
    __syncthreads();
    if (w == 0) {
        int y = ws[lane];
#pragma unroll
        for (int o = 1; o < 32; o <<= 1) {
            int z = __shfl_up_sync(0xffffffffu, y, o);
            if (lane >= o) y += z;
        }
        ws[lane] = y;
    }
    __syncthreads();
    int incl = x + (w ? ws[w - 1] : 0);
    int base = d_boff[blockIdx.x];
    int excl = base + incl - v;
    if (i < N_NODES) {
        d_rowptr[i] = excl;
        d_wpos[i] = excl;
        if (i == N_NODES - 1) d_rowptr[N_NODES] = excl + v;
    }
}
__global__ void fill_kernel(const int* __restrict__ src,
                            const int* __restrict__ dst) {
    int e = blockIdx.x * blockDim.x + threadIdx.x;
    if (e >= N_EDGES) return;
    int p = atomicAdd(&d_wpos[dst[e]], 1);
    d_csr_src[p] = src[e];
}

// ---------------------------------------------------------------------------
// Graph pooling (of z_last) + head (fold W2_3/b2_3, then MLP)
// ---------------------------------------------------------------------------
__global__ void zero_g_kernel() {
    int t = blockIdx.x * blockDim.x + threadIdx.x;
    if (t < NUM_GRAPHS * HIDDEN) d_g[t] = 0.f;
    if (t < NUM_GRAPHS) d_gcnt[t] = 0;
}
__global__ void pool_kernel(const int* __restrict__ batch) {
    int t = blockIdx.x * blockDim.x + threadIdx.x;
    int node = t >> 5;
    if (node >= N_NODES) return;
    int lane = t & 31;
    int gidx = __ldg(&batch[node]);
    float4 v = *(const float4*)&d_zB[node * HIDDEN + (lane << 2)];
    float* p = &d_g[gidx * HIDDEN + (lane << 2)];
    asm volatile("red.global.add.v4.f32 [%0], {%1,%2,%3,%4};"
                 :: "l"(p), "f"(v.x), "f"(v.y), "f"(v.z), "f"(v.w)
                 : "memory");
    if (lane == 0) atomicAdd(&d_gcnt[gidx], 1);
}
// gh = gpool @ W2_3 + cnt*b2_3 ; then 128->64(relu)->32(relu)->1
__global__ __launch_bounds__(128) void head_kernel(
    const float* __restrict__ W2c, const float* __restrict__ b2c,
    const float* __restrict__ W1, const float* __restrict__ b1,
    const float* __restrict__ W2, const float* __restrict__ b2,
    const float* __restrict__ W3, const float* __restrict__ b3,
    float* __restrict__ out) {
    __shared__ float sg[128];
    __shared__ float gh[128];
    __shared__ float s1[64];
    int g = blockIdx.x;
    int tid = threadIdx.x;

    sg[tid] = d_g[g * 128 + tid];
    __syncthreads();
    float cnt = (float)d_gcnt[g];

    float a = cnt * __ldg(&b2c[tid]);
#pragma unroll 8
    for (int k = 0; k < 128; k++) a = fmaf(sg[k], W2c[k * 128 + tid], a);
    gh[tid] = a;
    __syncthreads();

    if (tid < 64) {
        float acc = __ldg(&b1[tid]);
#pragma unroll 8
        for (int k = 0; k < 128; k++) acc = fmaf(gh[k], W1[k * 64 + tid], acc);
        s1[tid] = fmaxf(acc, 0.f);
    }
    __syncthreads();

    if (tid < 32) {
        float a2 = __ldg(&b2[tid]);
#pragma unroll 8
        for (int k = 0; k < 64; k++) a2 = fmaf(s1[k], W2[k * 32 + tid], a2);
        a2 = fmaxf(a2, 0.f);
        float t3 = a2 * __ldg(&W3[tid]);
#pragma unroll
        for (int o = 16; o; o >>= 1) t3 += __shfl_down_sync(0xffffffffu, t3, o);
        if (tid == 0) out[g] = t3 + __ldg(&b3[0]);
    }
}

// ---------------------------------------------------------------------------
extern "C" void kernel_launch(void* const* d_in, const int* in_sizes, int n_in,
                              void* d_out, int out_size) {
    const int*   x        = (const int*)d_in[0];
    const int*   edge_idx = (const int*)d_in[1];
    const int*   src      = edge_idx;
    const int*   dst      = edge_idx + N_EDGES;
    const int*   batch    = (const int*)d_in[3];
    const float* node_emb = (const float*)d_in[4];
    // d_in[2] (edge_attr) and d_in[5] (edge_emb) are dead in the reference.
    const float* conv_W1  = (const float*)d_in[6];
    const float* conv_b1  = (const float*)d_in[7];
    const float* conv_W2  = (const float*)d_in[8];
    const float* conv_b2  = (const float*)d_in[9];
    const float* mlp_W1   = (const float*)d_in[10];
    const float* mlp_b1   = (const float*)d_in[11];
    const float* mlp_W2   = (const float*)d_in[12];
    const float* mlp_b2   = (const float*)d_in[13];
    const float* mlp_W3   = (const float*)d_in[14];
    const float* mlp_b3   = (const float*)d_in[15];
    float* out = (float*)d_out;

    cudaFuncSetAttribute(layer_kernel<true>,
                         cudaFuncAttributeMaxDynamicSharedMemorySize, SMEMB);
    cudaFuncSetAttribute(layer_kernel<false>,
                         cudaFuncAttributeMaxDynamicSharedMemorySize, SMEMB);

    prep_w0_kernel<<<(HIDDEN * HIDDEN + 255) / 256, 256>>>(conv_W1);
    prep_compose_kernel<<<(3 * HIDDEN * HIDDEN + 255) / 256, 256>>>(conv_W1, conv_W2);
    prep_cvec_kernel<<<2, 256>>>(conv_W1, conv_b2);
    zero_deg_kernel<<<(N_NODES + 255) / 256, 256>>>();
    hist_kernel<<<(N_EDGES + 255) / 256, 256>>>(dst);
    scanA_kernel<<<SCAN_BLKS, 1024>>>();
    scanB_kernel<<<1, 128>>>();
    scanC_kernel<<<SCAN_BLKS, 1024>>>();
    fill_kernel<<<(N_EDGES + 255) / 256, 256>>>(src, dst);

    // z-state ping-pong: L0 emb->zA, L1 zA->zB, L2 zB->zA, L3 zA->zB
    layer_kernel<true><<<GRID_M, 256, SMEMB>>>(
        0, 0, 0, conv_b1 + 0 * HIDDEN, x, node_emb);
    layer_kernel<false><<<GRID_M, 256, SMEMB>>>(
        0, 1, 1, conv_b1 + 1 * HIDDEN, x, node_emb);
    layer_kernel<false><<<GRID_M, 256, SMEMB>>>(
        1, 0, 2, conv_b1 + 2 * HIDDEN, x, node_emb);
    layer_kernel<false><<<GRID_M, 256, SMEMB>>>(
        0, 1, 3, conv_b1 + 3 * HIDDEN, x, node_emb);

    zero_g_kernel<<<(NUM_GRAPHS * HIDDEN + 255) / 256, 256>>>();
    pool_kernel<<<(N_NODES * 32 + 255) / 256, 256>>>(batch);
    head_kernel<<<NUM_GRAPHS, 128>>>(
        conv_W2 + 3 * HIDDEN * HIDDEN, conv_b2 + 3 * HIDDEN,
        mlp_W1, mlp_b1, mlp_W2, mlp_b2, mlp_W3, mlp_b3, out);
}